// round 8
// baseline (speedup 1.0000x reference)
#include <cuda_runtime.h>
#include <cstdint>
#include <math.h>

// ---------------- problem constants ----------------
#define BB 8
#define TT 4096
#define DD 256
#define MM (BB*TT)      // 32768
#define KK 512          // 2*D
#define NCH 2048        // B*D

// scan chunking
#define CHUNK 128
#define NCHUNK (TT/CHUNK)   // 32

// mma.sync GEMM tiling
#define BM 128
#define BN 128
#define BK 16               // K per chunk (2 ktiles of k=8)
#define NCK (KK/BK)         // 32 chunks
#define TPB 256

// smem: fragment-layout buffers, double buffered
// per buffer (floats): AH[0..2048) AL[2048..4096) BH[4096..6144) BL[6144..8192)
#define FBUF 8192
#define SM_BYTES (2 * FBUF * 4)    // 64 KB

// ---------------- scratch (allocation-free) ----------------
__device__ float g_U[(size_t)MM * KK];   // 64 MB
__device__ float g_S[(size_t)MM * KK];   // 64 MB
__device__ float g_E[2 * NCHUNK * NCH];
__device__ float g_C[2 * NCHUNK * NCH];

// ---------------- helpers ----------------
// fp32 -> (tf32 hi bits, tf32 lo bits) split for 3xTF32 emulation
__device__ __forceinline__ void split32(float a, uint32_t& hi, uint32_t& lo) {
    uint32_t h;
    asm("cvt.rna.tf32.f32 %0, %1;" : "=r"(h) : "f"(a));
    hi = h;
    float res = a - __uint_as_float(h);
    uint32_t l;
    asm("cvt.rna.tf32.f32 %0, %1;" : "=r"(l) : "f"(res));
    lo = l;
}

#define MMA_TF32(acc, a, b0v, b1v)                                              \
    asm volatile("mma.sync.aligned.m16n8k8.row.col.f32.tf32.tf32.f32 "          \
        "{%0,%1,%2,%3}, {%4,%5,%6,%7}, {%8,%9}, {%0,%1,%2,%3};"                 \
        : "+f"((acc)[0]), "+f"((acc)[1]), "+f"((acc)[2]), "+f"((acc)[3])        \
        : "r"((a).x), "r"((a).y), "r"((a).z), "r"((a).w), "r"(b0v), "r"(b1v))

// ---------------- 3xTF32 mma.sync GEMM ----------------
// C[m,n] = sum_k A[m,k] * W[n,k] + bias[n]
// MODE 0: A = concat(x_re,x_im) along k; W = Wm; C = g_U (ldc=512)
// MODE 1: A = g_S; W = Wo (n<512) else Wg (gate: clip(sigmoid)); C = out (ldc=768)
//
// Fragment smem layout (per mma.m16n8k8 thread ownership):
//  A elem (m,k): mt=m>>4, kt=k>>3, lane=(m&7)*4+(k&3), reg=((m>>3)&1)|(((k>>2)&1)<<1)
//     idx = kt*1024 + mt*128 + lane*4 + reg
//  B elem (n,k): nt=n>>3, kt=k>>3, lane=(n&7)*4+(k&3), reg=(k>>2)&1
//     idx = kt*1024 + nt*64 + lane*2 + reg
template <int MODE>
__global__ void __launch_bounds__(TPB)
tc_gemm(const float* __restrict__ Are, const float* __restrict__ Aim,
        const float* __restrict__ W0, const float* __restrict__ W1,
        const float* __restrict__ bias0, const float* __restrict__ bias1,
        float* __restrict__ Cout, int ldc)
{
    extern __shared__ float sm[];

    const int tid = threadIdx.x;
    const int wid = tid >> 5;
    const int lane = tid & 31;
    const int warp_m = wid & 3;      // 0..3 -> rows warp_m*32
    const int warp_n = wid >> 2;     // 0..1 -> cols warp_n*64
    const int m0 = blockIdx.y * BM;
    const int n0 = blockIdx.x * BN;

    const bool gate = (MODE == 1) && (n0 >= 512);
    const float* __restrict__ W = gate ? W1 : W0;
    const int nW = gate ? (n0 - 512) : n0;

    // loader indexing: two float4 per thread per tile (A and B each)
    // i = it*256 + tid; r = i>>2 (row 0..127), c4 = i&3 (k-group of 4)
    const int r0 = tid >> 2, c40 = tid & 3;
    const int r1 = (256 + tid) >> 2, c41 = tid & 3;   // r1 = r0+64

    float4 fa[2], fb[2];

    auto fetch = [&](int c) {
        const int k0 = c * BK;
        const float* Ab;
        int lda;
        if (MODE == 0) {
            lda = DD;
            Ab = (k0 < DD) ? (Are + (size_t)m0 * DD + k0)
                           : (Aim + (size_t)m0 * DD + (k0 - DD));
        } else {
            lda = KK;
            Ab = g_S + (size_t)m0 * KK + k0;
        }
        fa[0] = *(const float4*)(Ab + (size_t)r0 * lda + c40 * 4);
        fa[1] = *(const float4*)(Ab + (size_t)r1 * lda + c41 * 4);
        const float* Bb = W + (size_t)nW * KK + k0;
        fb[0] = *(const float4*)(Bb + (size_t)r0 * KK + c40 * 4);
        fb[1] = *(const float4*)(Bb + (size_t)r1 * KK + c41 * 4);
    };

    auto store_smem = [&](int buf) {
        float* AH = sm + buf * FBUF;
        float* AL = AH + 2048;
        float* BH = AH + 4096;
        float* BL = AH + 6144;
#pragma unroll
        for (int it = 0; it < 2; it++) {
            const int r = it ? r1 : r0;
            const int c4 = it ? c41 : c40;
            const int kt = c4 >> 1;
            // A: reg = ((r>>3)&1) | ((c4&1)<<1); lane = (r&7)*4 + j
            {
                const int reg = ((r >> 3) & 1) | ((c4 & 1) << 1);
                const int mt = r >> 4;
                const int base = kt * 1024 + mt * 128 + (r & 7) * 16 + reg;
                const float v[4] = {fa[it].x, fa[it].y, fa[it].z, fa[it].w};
#pragma unroll
                for (int j = 0; j < 4; j++) {
                    uint32_t h, l;
                    split32(v[j], h, l);
                    AH[base + j * 4] = __uint_as_float(h);
                    AL[base + j * 4] = __uint_as_float(l);
                }
            }
            // B: reg = c4&1; lane = (r&7)*4 + j
            {
                const int reg = c4 & 1;
                const int nt = r >> 3;
                const int base = kt * 1024 + nt * 64 + (r & 7) * 8 + reg;
                const float v[4] = {fb[it].x, fb[it].y, fb[it].z, fb[it].w};
#pragma unroll
                for (int j = 0; j < 4; j++) {
                    uint32_t h, l;
                    split32(v[j], h, l);
                    BH[base + j * 2] = __uint_as_float(h);
                    BL[base + j * 2] = __uint_as_float(l);
                }
            }
        }
    };

    float acc[2][8][4];
#pragma unroll
    for (int mi = 0; mi < 2; mi++)
#pragma unroll
        for (int ni = 0; ni < 8; ni++)
#pragma unroll
            for (int q = 0; q < 4; q++) acc[mi][ni][q] = 0.0f;

    // prologue
    fetch(0);
    store_smem(0);
    __syncthreads();

#pragma unroll 1
    for (int c = 0; c < NCK; c++) {
        const int buf = c & 1;
        const bool has_next = (c + 1 < NCK);
        if (has_next) fetch(c + 1);

        const float* AH = sm + buf * FBUF;
        const float* AL = AH + 2048;
        const float* BH = AH + 4096;
        const float* BL = AH + 6144;

#pragma unroll
        for (int kt = 0; kt < 2; kt++) {
            uint4 ah[2], al[2];
#pragma unroll
            for (int mi = 0; mi < 2; mi++) {
                const int mt = warp_m * 2 + mi;
                const int ia = kt * 1024 + mt * 128 + lane * 4;
                ah[mi] = *(const uint4*)(AH + ia);
                al[mi] = *(const uint4*)(AL + ia);
            }
#pragma unroll
            for (int ni = 0; ni < 8; ni++) {
                const int nt = warp_n * 8 + ni;
                const int ib = kt * 1024 + nt * 64 + lane * 2;
                const uint2 bh = *(const uint2*)(BH + ib);
                const uint2 bl = *(const uint2*)(BL + ib);
#pragma unroll
                for (int mi = 0; mi < 2; mi++) {
                    MMA_TF32(acc[mi][ni], ah[mi], bh.x, bh.y);
                    MMA_TF32(acc[mi][ni], ah[mi], bl.x, bl.y);
                    MMA_TF32(acc[mi][ni], al[mi], bh.x, bh.y);
                }
            }
        }

        if (has_next) {
            store_smem(buf ^ 1);
            __syncthreads();
        }
    }

    // ---- epilogue ----
    const int g = lane >> 2, t = lane & 3;
    float* __restrict__ C = (MODE == 0) ? g_U : Cout;
    const float* bptr = (MODE == 0) ? (bias0 + n0)
                      : (gate ? (bias1 + n0 - 512) : (bias0 + n0));

#pragma unroll
    for (int mi = 0; mi < 2; mi++) {
        const int R0 = m0 + warp_m * 32 + mi * 16 + g;
#pragma unroll
        for (int ni = 0; ni < 8; ni++) {
            const int coff = warp_n * 64 + ni * 8 + 2 * t;
            const float2 bb = *(const float2*)(bptr + coff);
            float v0 = acc[mi][ni][0] + bb.x;
            float v1 = acc[mi][ni][1] + bb.y;
            float v2 = acc[mi][ni][2] + bb.x;
            float v3 = acc[mi][ni][3] + bb.y;
            if (gate) {
                v0 = fminf(fmaxf(1.0f / (1.0f + __expf(-v0)), 0.01f), 0.99f);
                v1 = fminf(fmaxf(1.0f / (1.0f + __expf(-v1)), 0.01f), 0.99f);
                v2 = fminf(fmaxf(1.0f / (1.0f + __expf(-v2)), 0.01f), 0.99f);
                v3 = fminf(fmaxf(1.0f / (1.0f + __expf(-v3)), 0.01f), 0.99f);
            }
            const int col = n0 + coff;
            *(float2*)(C + (size_t)R0 * ldc + col)       = make_float2(v0, v1);
            *(float2*)(C + (size_t)(R0 + 8) * ldc + col) = make_float2(v2, v3);
        }
    }
}

// ---------------- chunk-parallel diagonal complex scan ----------------
__global__ void __launch_bounds__(256)
scan_passA(const float* __restrict__ decay_re, const float* __restrict__ decay_im)
{
    const int id = blockIdx.x * blockDim.x + threadIdx.x;
    const int ch = id & (NCH - 1);
    const int c  = id >> 11;
    const int b = ch >> 8;
    const int d = ch & 255;

    const float dr = 1.0f / (1.0f + expf(-decay_re[d]));
    const float di = decay_im[d];

    const float* __restrict__ U = g_U + ((size_t)b * TT + (size_t)c * CHUNK) * KK + d;

    float sr = 0.0f, si = 0.0f;
#pragma unroll 4
    for (int j = 0; j < CHUNK; j++) {
        const float ur = __ldg(U + (size_t)j * KK);
        const float ui = __ldg(U + (size_t)j * KK + 256);
        const float nr = fmaf(sr, dr, fmaf(-si, di, ur));
        const float ni = fmaf(sr, di, fmaf(si, dr, ui));
        sr = nr; si = ni;
    }
    g_E[c * NCH + ch]                = sr;
    g_E[NCHUNK * NCH + c * NCH + ch] = si;
}

__global__ void __launch_bounds__(256)
scan_passB(const float* __restrict__ s0_re, const float* __restrict__ s0_im,
           const float* __restrict__ decay_re, const float* __restrict__ decay_im)
{
    const int id = blockIdx.x * blockDim.x + threadIdx.x;
    const int d = id & 255;

    const float dr = 1.0f / (1.0f + expf(-decay_re[d]));
    const float di = decay_im[d];

    float pr = dr, pi = di;
#pragma unroll
    for (int s = 0; s < 7; s++) {     // d^128
        const float nr = pr * pr - pi * pi;
        const float ni = 2.0f * pr * pi;
        pr = nr; pi = ni;
    }

    float cr = s0_re[id];
    float ci = s0_im[id];
#pragma unroll
    for (int c = 0; c < NCHUNK; c++) {
        g_C[c * NCH + id]                = cr;
        g_C[NCHUNK * NCH + c * NCH + id] = ci;
        const float er = g_E[c * NCH + id];
        const float ei = g_E[NCHUNK * NCH + c * NCH + id];
        const float nr = fmaf(cr, pr, fmaf(-ci, pi, er));
        const float ni = fmaf(cr, pi, fmaf(ci, pr, ei));
        cr = nr; ci = ni;
    }
}

__global__ void __launch_bounds__(256)
scan_passC(const float* __restrict__ decay_re, const float* __restrict__ decay_im)
{
    const int id = blockIdx.x * blockDim.x + threadIdx.x;
    const int ch = id & (NCH - 1);
    const int c  = id >> 11;
    const int b = ch >> 8;
    const int d = ch & 255;

    const float dr = 1.0f / (1.0f + expf(-decay_re[d]));
    const float di = decay_im[d];

    const size_t off = ((size_t)b * TT + (size_t)c * CHUNK) * KK + d;
    const float* __restrict__ U = g_U + off;
    float*       __restrict__ S = g_S + off;

    float sr = g_C[c * NCH + ch];
    float si = g_C[NCHUNK * NCH + c * NCH + ch];

#pragma unroll 4
    for (int j = 0; j < CHUNK; j++) {
        const float ur = __ldg(U + (size_t)j * KK);
        const float ui = __ldg(U + (size_t)j * KK + 256);
        const float nr = fmaf(sr, dr, fmaf(-si, di, ur));
        const float ni = fmaf(sr, di, fmaf(si, dr, ui));
        sr = nr; si = ni;
        S[(size_t)j * KK]       = nr;
        S[(size_t)j * KK + 256] = ni;
    }
}

// ---------------- launch ----------------
extern "C" void kernel_launch(void* const* d_in, const int* in_sizes, int n_in,
                              void* d_out, int out_size)
{
    (void)in_sizes; (void)n_in; (void)out_size;
    const float* x_re     = (const float*)d_in[0];
    const float* x_im     = (const float*)d_in[1];
    const float* s0_re    = (const float*)d_in[2];
    const float* s0_im    = (const float*)d_in[3];
    const float* decay_re = (const float*)d_in[4];
    const float* decay_im = (const float*)d_in[5];
    const float* Wm       = (const float*)d_in[6];
    const float* bm       = (const float*)d_in[7];
    const float* Wo       = (const float*)d_in[8];
    const float* bo       = (const float*)d_in[9];
    const float* Wg       = (const float*)d_in[10];
    const float* bg       = (const float*)d_in[11];
    float* out = (float*)d_out;

    static bool configured = false;
    if (!configured) {
        cudaFuncSetAttribute(tc_gemm<0>, cudaFuncAttributeMaxDynamicSharedMemorySize, SM_BYTES);
        cudaFuncSetAttribute(tc_gemm<1>, cudaFuncAttributeMaxDynamicSharedMemorySize, SM_BYTES);
        configured = true;
    }

    // 1) u = x_cat @ Wm^T + bm  -> g_U   (N=512 -> 4 tiles of 128)
    tc_gemm<0><<<dim3(KK / BN, MM / BM), TPB, SM_BYTES>>>(
        x_re, x_im, Wm, nullptr, bm, nullptr, nullptr, KK);

    // 2) chunk-parallel diagonal complex scan g_U -> g_S
    scan_passA<<<(NCH * NCHUNK) / 256, 256>>>(decay_re, decay_im);
    scan_passB<<<NCH / 256, 256>>>(s0_re, s0_im, decay_re, decay_im);
    scan_passC<<<(NCH * NCHUNK) / 256, 256>>>(decay_re, decay_im);

    // 3) [source | gate] = s_cat @ [Wo;Wg]^T + [bo;bg]  (N=768 -> 6 tiles of 128)
    tc_gemm<1><<<dim3(768 / BN, MM / BM), TPB, SM_BYTES>>>(
        nullptr, nullptr, Wo, Wg, bo, bg, out, 768);
}

// round 10
// speedup vs baseline: 1.2832x; 1.2832x over previous
#include <cuda_runtime.h>
#include <cuda_fp16.h>
#include <cstdint>
#include <math.h>

// ---------------- problem constants ----------------
#define BB 8
#define TT 4096
#define DD 256
#define MM (BB*TT)      // 32768
#define KK 512          // 2*D
#define NCH 2048        // B*D

// scan chunking
#define CHUNK 128
#define NCHUNK (TT/CHUNK)   // 32

// mma.sync fp16 GEMM tiling
#define BM 128
#define BN 128
#define BK 32               // K per chunk (2 ktiles of k=16)
#define NCK (KK/BK)         // 16 chunks
#define TPB 256

// smem per buffer (b32 words):
//  AH [0,2048) AL [2048,4096) BH [4096,6144) BL [6144,8192)
// fragment layouts:
//  A: idx = kt*1024 + mt*128 + lane*4 + (rh*2 + kh)   (uint4 per lane)
//  B: idx = kt*1024 + nt*64  + lane*2 + kh            (uint2 per lane)
#define FBUF 8192
#define SM_BYTES (2 * FBUF * 4)    // 64 KB

// ---------------- scratch (allocation-free) ----------------
__device__ float g_U[(size_t)MM * KK];   // 64 MB
__device__ float g_S[(size_t)MM * KK];   // 64 MB
__device__ float g_E[2 * NCHUNK * NCH];
__device__ float g_C[2 * NCHUNK * NCH];

// ---------------- helpers ----------------
// split a pair of fp32 into fp16x2 hi + fp16x2 lo (3xFP16 emulation limbs)
__device__ __forceinline__ void split2(float e0, float e1, uint32_t& hi, uint32_t& lo) {
    __half2 h = __floats2half2_rn(e0, e1);       // lo half = e0, hi half = e1
    float2 b = __half22float2(h);
    __half2 l = __floats2half2_rn(e0 - b.x, e1 - b.y);
    hi = *(uint32_t*)&h;
    lo = *(uint32_t*)&l;
}

// a = uint4 from smem in order (rh0kh0, rh0kh1, rh1kh0, rh1kh1)
// mma A operand order is (rh0kh0, rh1kh0, rh0kh1, rh1kh1) -> pass x,z,y,w
#define MMA_F16(acc, a, b)                                                      \
    asm volatile("mma.sync.aligned.m16n8k16.row.col.f32.f16.f16.f32 "           \
        "{%0,%1,%2,%3}, {%4,%5,%6,%7}, {%8,%9}, {%0,%1,%2,%3};"                 \
        : "+f"((acc)[0]), "+f"((acc)[1]), "+f"((acc)[2]), "+f"((acc)[3])        \
        : "r"((a).x), "r"((a).z), "r"((a).y), "r"((a).w), "r"((b).x), "r"((b).y))

// ---------------- 3xFP16 mma.sync GEMM ----------------
// C[m,n] = sum_k A[m,k] * W[n,k] + bias[n]
// MODE 0: A = concat(x_re,x_im) along k; W = Wm; C = g_U (ldc=512)
// MODE 1: A = g_S; W = Wo (n<512) else Wg (gate: clip(sigmoid)); C = out (ldc=768)
template <int MODE>
__global__ void __launch_bounds__(TPB)
tc_gemm(const float* __restrict__ Are, const float* __restrict__ Aim,
        const float* __restrict__ W0, const float* __restrict__ W1,
        const float* __restrict__ bias0, const float* __restrict__ bias1,
        float* __restrict__ Cout, int ldc)
{
    extern __shared__ uint32_t sm[];

    const int tid = threadIdx.x;
    const int wid = tid >> 5;
    const int lane = tid & 31;
    const int warp_m = wid & 3;      // rows warp_m*32
    const int warp_n = wid >> 2;     // cols warp_n*64
    const int m0 = blockIdx.y * BM;
    const int n0 = blockIdx.x * BN;

    const bool gate = (MODE == 1) && (n0 >= 512);
    const float* __restrict__ W = gate ? W1 : W0;
    const int nW = gate ? (n0 - 512) : n0;

    // loader mapping: r = (tid&15) + warp*16 (0..127), h = ktile (0/1)
    const int lr = (tid & 15) + ((tid >> 5) << 4);
    const int lh = (tid >> 4) & 1;
    const int lmt = lr >> 4;          // A m-tile
    const int lrh = (lr >> 3) & 1;    // A row-half within tile
    const int lnt = lr >> 3;          // B n-tile
    const int lg  = lr & 7;           // group within 8
    const int lrot = ((lr >> 1) + (lr >> 3)) & 3;   // bank rotation

    float4 fa[4], fb[4];

    auto fetch = [&](int c) {
        const int k0 = c * BK + lh * 16;
        const float* Ab;
        int lda;
        if (MODE == 0) {
            lda = DD;
            Ab = (k0 < DD) ? (Are + (size_t)(m0 + lr) * DD + k0)
                           : (Aim + (size_t)(m0 + lr) * DD + (k0 - DD));
        } else {
            lda = KK;
            Ab = g_S + (size_t)(m0 + lr) * KK + k0;
        }
#pragma unroll
        for (int j = 0; j < 4; j++) fa[j] = *(const float4*)(Ab + j * 4);
        const float* Bb = W + (size_t)(nW + lr) * KK + k0;
#pragma unroll
        for (int j = 0; j < 4; j++) fb[j] = *(const float4*)(Bb + j * 4);
    };

    auto store_smem = [&](int buf) {
        uint32_t* base = sm + buf * FBUF;
        const float* va = (const float*)fa;
        const float* vb = (const float*)fb;
#pragma unroll
        for (int t0 = 0; t0 < 4; t0++) {
            const int t = (t0 + lrot) & 3;
            // A: words (rh,kh0),(rh,kh1) at lane (lg*4+t)
            {
                uint32_t h0, l0, h1, l1;
                split2(va[2 * t], va[2 * t + 1], h0, l0);
                split2(va[8 + 2 * t], va[9 + 2 * t], h1, l1);
                const int idx = lh * 1024 + lmt * 128 + (lg * 4 + t) * 4 + lrh * 2;
                *(uint2*)(base + idx)        = make_uint2(h0, h1);
                *(uint2*)(base + 2048 + idx) = make_uint2(l0, l1);
            }
            // B: words (kh0),(kh1) at lane (lg*4+t)
            {
                uint32_t h0, l0, h1, l1;
                split2(vb[2 * t], vb[2 * t + 1], h0, l0);
                split2(vb[8 + 2 * t], vb[9 + 2 * t], h1, l1);
                const int idx = lh * 1024 + lnt * 64 + (lg * 4 + t) * 2;
                *(uint2*)(base + 4096 + idx) = make_uint2(h0, h1);
                *(uint2*)(base + 6144 + idx) = make_uint2(l0, l1);
            }
        }
    };

    float acc[2][8][4];
#pragma unroll
    for (int mi = 0; mi < 2; mi++)
#pragma unroll
        for (int ni = 0; ni < 8; ni++)
#pragma unroll
            for (int q = 0; q < 4; q++) acc[mi][ni][q] = 0.0f;

    // prologue
    fetch(0);
    store_smem(0);
    __syncthreads();

#pragma unroll 1
    for (int c = 0; c < NCK; c++) {
        const int buf = c & 1;
        const bool has_next = (c + 1 < NCK);
        if (has_next) fetch(c + 1);

        const uint32_t* base = sm + buf * FBUF;

#pragma unroll
        for (int kt = 0; kt < 2; kt++) {
            uint4 ah[2], al[2];
#pragma unroll
            for (int mi = 0; mi < 2; mi++) {
                const int ia = kt * 1024 + (warp_m * 2 + mi) * 128 + lane * 4;
                ah[mi] = *(const uint4*)(base + ia);
                al[mi] = *(const uint4*)(base + 2048 + ia);
            }
#pragma unroll
            for (int ni = 0; ni < 8; ni++) {
                const int ib = kt * 1024 + (warp_n * 8 + ni) * 64 + lane * 2;
                const uint2 bh = *(const uint2*)(base + 4096 + ib);
                const uint2 bl = *(const uint2*)(base + 6144 + ib);
#pragma unroll
                for (int mi = 0; mi < 2; mi++) {
                    MMA_F16(acc[mi][ni], ah[mi], bh);
                    MMA_F16(acc[mi][ni], ah[mi], bl);
                    MMA_F16(acc[mi][ni], al[mi], bh);
                }
            }
        }

        if (has_next) {
            store_smem(buf ^ 1);
            __syncthreads();
        }
    }

    // ---- epilogue ----
    const int g = lane >> 2, t = lane & 3;
    float* __restrict__ C = (MODE == 0) ? g_U : Cout;
    const float* bptr = (MODE == 0) ? (bias0 + n0)
                      : (gate ? (bias1 + n0 - 512) : (bias0 + n0));

#pragma unroll
    for (int mi = 0; mi < 2; mi++) {
        const int R0 = m0 + warp_m * 32 + mi * 16 + g;
#pragma unroll
        for (int ni = 0; ni < 8; ni++) {
            const int coff = warp_n * 64 + ni * 8 + 2 * t;
            const float2 bb = *(const float2*)(bptr + coff);
            float v0 = acc[mi][ni][0] + bb.x;
            float v1 = acc[mi][ni][1] + bb.y;
            float v2 = acc[mi][ni][2] + bb.x;
            float v3 = acc[mi][ni][3] + bb.y;
            if (gate) {
                v0 = fminf(fmaxf(1.0f / (1.0f + __expf(-v0)), 0.01f), 0.99f);
                v1 = fminf(fmaxf(1.0f / (1.0f + __expf(-v1)), 0.01f), 0.99f);
                v2 = fminf(fmaxf(1.0f / (1.0f + __expf(-v2)), 0.01f), 0.99f);
                v3 = fminf(fmaxf(1.0f / (1.0f + __expf(-v3)), 0.01f), 0.99f);
            }
            const int col = n0 + coff;
            *(float2*)(C + (size_t)R0 * ldc + col)       = make_float2(v0, v1);
            *(float2*)(C + (size_t)(R0 + 8) * ldc + col) = make_float2(v2, v3);
        }
    }
}

// ---------------- chunk-parallel diagonal complex scan ----------------
__global__ void __launch_bounds__(256)
scan_passA(const float* __restrict__ decay_re, const float* __restrict__ decay_im)
{
    const int id = blockIdx.x * blockDim.x + threadIdx.x;
    const int ch = id & (NCH - 1);
    const int c  = id >> 11;
    const int b = ch >> 8;
    const int d = ch & 255;

    const float dr = 1.0f / (1.0f + expf(-decay_re[d]));
    const float di = decay_im[d];

    const float* __restrict__ U = g_U + ((size_t)b * TT + (size_t)c * CHUNK) * KK + d;

    float sr = 0.0f, si = 0.0f;
#pragma unroll 4
    for (int j = 0; j < CHUNK; j++) {
        const float ur = __ldg(U + (size_t)j * KK);
        const float ui = __ldg(U + (size_t)j * KK + 256);
        const float nr = fmaf(sr, dr, fmaf(-si, di, ur));
        const float ni = fmaf(sr, di, fmaf(si, dr, ui));
        sr = nr; si = ni;
    }
    g_E[c * NCH + ch]                = sr;
    g_E[NCHUNK * NCH + c * NCH + ch] = si;
}

__global__ void __launch_bounds__(256)
scan_passB(const float* __restrict__ s0_re, const float* __restrict__ s0_im,
           const float* __restrict__ decay_re, const float* __restrict__ decay_im)
{
    const int id = blockIdx.x * blockDim.x + threadIdx.x;
    const int d = id & 255;

    const float dr = 1.0f / (1.0f + expf(-decay_re[d]));
    const float di = decay_im[d];

    float pr = dr, pi = di;
#pragma unroll
    for (int s = 0; s < 7; s++) {     // d^128
        const float nr = pr * pr - pi * pi;
        const float ni = 2.0f * pr * pi;
        pr = nr; pi = ni;
    }

    float cr = s0_re[id];
    float ci = s0_im[id];
#pragma unroll
    for (int c = 0; c < NCHUNK; c++) {
        g_C[c * NCH + id]                = cr;
        g_C[NCHUNK * NCH + c * NCH + id] = ci;
        const float er = g_E[c * NCH + id];
        const float ei = g_E[NCHUNK * NCH + c * NCH + id];
        const float nr = fmaf(cr, pr, fmaf(-ci, pi, er));
        const float ni = fmaf(cr, pi, fmaf(ci, pr, ei));
        cr = nr; ci = ni;
    }
}

__global__ void __launch_bounds__(256)
scan_passC(const float* __restrict__ decay_re, const float* __restrict__ decay_im)
{
    const int id = blockIdx.x * blockDim.x + threadIdx.x;
    const int ch = id & (NCH - 1);
    const int c  = id >> 11;
    const int b = ch >> 8;
    const int d = ch & 255;

    const float dr = 1.0f / (1.0f + expf(-decay_re[d]));
    const float di = decay_im[d];

    const size_t off = ((size_t)b * TT + (size_t)c * CHUNK) * KK + d;
    const float* __restrict__ U = g_U + off;
    float*       __restrict__ S = g_S + off;

    float sr = g_C[c * NCH + ch];
    float si = g_C[NCHUNK * NCH + c * NCH + ch];

#pragma unroll 4
    for (int j = 0; j < CHUNK; j++) {
        const float ur = __ldg(U + (size_t)j * KK);
        const float ui = __ldg(U + (size_t)j * KK + 256);
        const float nr = fmaf(sr, dr, fmaf(-si, di, ur));
        const float ni = fmaf(sr, di, fmaf(si, dr, ui));
        sr = nr; si = ni;
        S[(size_t)j * KK]       = nr;
        S[(size_t)j * KK + 256] = ni;
    }
}

// ---------------- launch ----------------
extern "C" void kernel_launch(void* const* d_in, const int* in_sizes, int n_in,
                              void* d_out, int out_size)
{
    (void)in_sizes; (void)n_in; (void)out_size;
    const float* x_re     = (const float*)d_in[0];
    const float* x_im     = (const float*)d_in[1];
    const float* s0_re    = (const float*)d_in[2];
    const float* s0_im    = (const float*)d_in[3];
    const float* decay_re = (const float*)d_in[4];
    const float* decay_im = (const float*)d_in[5];
    const float* Wm       = (const float*)d_in[6];
    const float* bm       = (const float*)d_in[7];
    const float* Wo       = (const float*)d_in[8];
    const float* bo       = (const float*)d_in[9];
    const float* Wg       = (const float*)d_in[10];
    const float* bg       = (const float*)d_in[11];
    float* out = (float*)d_out;

    static bool configured = false;
    if (!configured) {
        cudaFuncSetAttribute(tc_gemm<0>, cudaFuncAttributeMaxDynamicSharedMemorySize, SM_BYTES);
        cudaFuncSetAttribute(tc_gemm<1>, cudaFuncAttributeMaxDynamicSharedMemorySize, SM_BYTES);
        configured = true;
    }

    // 1) u = x_cat @ Wm^T + bm  -> g_U
    tc_gemm<0><<<dim3(KK / BN, MM / BM), TPB, SM_BYTES>>>(
        x_re, x_im, Wm, nullptr, bm, nullptr, nullptr, KK);

    // 2) chunk-parallel diagonal complex scan g_U -> g_S
    scan_passA<<<(NCH * NCHUNK) / 256, 256>>>(decay_re, decay_im);
    scan_passB<<<NCH / 256, 256>>>(s0_re, s0_im, decay_re, decay_im);
    scan_passC<<<(NCH * NCHUNK) / 256, 256>>>(decay_re, decay_im);

    // 3) [source | gate] = s_cat @ [Wo;Wg]^T + [bo;bg]
    tc_gemm<1><<<dim3(768 / BN, MM / BM), TPB, SM_BYTES>>>(
        nullptr, nullptr, Wo, Wg, bo, bg, out, 768);
}

// round 11
// speedup vs baseline: 1.4428x; 1.1244x over previous
#include <cuda_runtime.h>
#include <cuda_fp16.h>
#include <cstdint>
#include <math.h>

// ---------------- problem constants ----------------
#define BB 8
#define TT 4096
#define DD 256
#define MM (BB*TT)      // 32768
#define KK 512          // 2*D
#define NCH 2048        // B*D

// scan chunking
#define CHUNK 128
#define NCHUNK (TT/CHUNK)   // 32

// mma.sync fp16 GEMM tiling
#define BM 128
#define BN 128
#define BK 32               // K per chunk (2 ktiles of k=16)
#define NCK (KK/BK)         // 16 chunks
#define TPB 256

// smem per buffer (b32 words): AH[0,2048) AL[2048,4096) BH[4096,6144) BL[6144,8192)
#define FBUF 8192
#define SM_BYTES (2 * FBUF * 4)    // 64 KB

// ---------------- scratch (allocation-free) ----------------
__device__ float  g_U[(size_t)MM * KK];    // 64 MB fp32 (scan input needs full precision)
__device__ __half g_Xh[(size_t)MM * KK];   // 32 MB: hi limb of concat(x_re,x_im)
__device__ __half g_Xl[(size_t)MM * KK];   // 32 MB: lo limb
__device__ __half g_Sh[(size_t)MM * KK];   // 32 MB: hi limb of scanned state
__device__ __half g_Sl[(size_t)MM * KK];   // 32 MB: lo limb
__device__ __half g_W0h[512 * 512], g_W0l[512 * 512];   // Wm limbs
__device__ __half g_W1h[768 * 512], g_W1l[768 * 512];   // [Wo;Wg] limbs
__device__ float g_E[2 * NCHUNK * NCH];
__device__ float g_C[2 * NCHUNK * NCH];

// ---------------- helpers ----------------
__device__ __forceinline__ void split_store4(const float4 v, __half* ph, __half* pl, size_t e) {
    __half2 h0 = __floats2half2_rn(v.x, v.y);
    __half2 h1 = __floats2half2_rn(v.z, v.w);
    float2 f0 = __half22float2(h0), f1 = __half22float2(h1);
    __half2 l0 = __floats2half2_rn(v.x - f0.x, v.y - f0.y);
    __half2 l1 = __floats2half2_rn(v.z - f1.x, v.w - f1.y);
    *(uint2*)(ph + e) = make_uint2(*(uint32_t*)&h0, *(uint32_t*)&h1);
    *(uint2*)(pl + e) = make_uint2(*(uint32_t*)&l0, *(uint32_t*)&l1);
}

// smem swizzles (pure functions of logical word index; conflict-free STS/LDS)
__device__ __forceinline__ int swzA(int idx) { return idx ^ (((idx >> 5) & 3) << 2); }
__device__ __forceinline__ int swzB(int idx) {
    return idx ^ ((((idx >> 5) & 1) | (((idx >> 6) & 1) << 1)) << 1);
}

// a = uint4 regs (rh0kh0, rh0kh1, rh1kh0, rh1kh1); mma wants x,z,y,w order
#define MMA_F16(acc, a, b)                                                      \
    asm volatile("mma.sync.aligned.m16n8k16.row.col.f32.f16.f16.f32 "           \
        "{%0,%1,%2,%3}, {%4,%5,%6,%7}, {%8,%9}, {%0,%1,%2,%3};"                 \
        : "+f"((acc)[0]), "+f"((acc)[1]), "+f"((acc)[2]), "+f"((acc)[3])        \
        : "r"((a).x), "r"((a).z), "r"((a).y), "r"((a).w), "r"((b).x), "r"((b).y))

// ---------------- pre-split kernels ----------------
__global__ void __launch_bounds__(256)
split_x(const float* __restrict__ xre, const float* __restrict__ xim)
{
    const size_t i = (size_t)blockIdx.x * blockDim.x + threadIdx.x;  // one float4
    const size_t e = i * 4;
    const int m = (int)(e >> 9);
    const int k = (int)(e & 511);
    const float4 v = (k < 256)
        ? *(const float4*)(xre + (size_t)m * 256 + k)
        : *(const float4*)(xim + (size_t)m * 256 + (k - 256));
    split_store4(v, g_Xh, g_Xl, e);
}

__global__ void __launch_bounds__(256)
split_w(const float* __restrict__ Wm, const float* __restrict__ Wo,
        const float* __restrict__ Wg)
{
    const size_t i = (size_t)blockIdx.x * blockDim.x + threadIdx.x;
    const size_t e = i * 4;
    if (e < (size_t)512 * 512) {
        split_store4(*(const float4*)(Wm + e), g_W0h, g_W0l, e);
    } else {
        const size_t e1 = e - (size_t)512 * 512;     // within [Wo;Wg] plane
        const int n = (int)(e1 >> 9), k = (int)(e1 & 511);
        const float* src = (n < 512) ? (Wo + (size_t)n * 512 + k)
                                     : (Wg + (size_t)(n - 512) * 512 + k);
        split_store4(*(const float4*)src, g_W1h, g_W1l, e1);
    }
}

// ---------------- 3xFP16 mma.sync GEMM (pre-split operands) ----------------
// C[m,n] = sum_k A[m,k] * W[n,k] + bias[n]
// MODE 0: A = g_X limbs; W = g_W0 limbs; C = g_U fp32 (ldc=512)
// MODE 1: A = g_S limbs; W = g_W1 limbs; gate cols (n>=512): clip(sigmoid); C = out (ldc=768)
template <int MODE>
__global__ void __launch_bounds__(TPB)
tc_gemm(const float* __restrict__ bias0, const float* __restrict__ bias1,
        float* __restrict__ Cout, int ldc)
{
    extern __shared__ uint32_t sm[];

    const int tid = threadIdx.x;
    const int wid = tid >> 5;
    const int lane = tid & 31;
    const int warp_m = wid & 3;      // rows warp_m*32
    const int warp_n = wid >> 2;     // cols warp_n*64
    const int m0 = blockIdx.y * BM;
    const int n0 = blockIdx.x * BN;

    const bool gate = (MODE == 1) && (n0 >= 512);

    const __half* __restrict__ Aph = (MODE == 0) ? g_Xh : g_Sh;
    const __half* __restrict__ Apl = (MODE == 0) ? g_Xl : g_Sl;
    const __half* __restrict__ Bph = (MODE == 0) ? g_W0h : g_W1h;
    const __half* __restrict__ Bpl = (MODE == 0) ? g_W0l : g_W1l;

    // loader mapping: row lr (0..127), ktile lh (0/1)
    const int lr = (tid & 15) + ((tid >> 5) << 4);
    const int lh = (tid >> 4) & 1;
    const int lmt = lr >> 4;          // A m-tile
    const int lrh = (lr >> 3) & 1;    // row-half within 16-row tile
    const int lnt = lr >> 3;          // B n-tile
    const int lg  = lr & 7;

    uint4 sa0, sa1, sl0, sl1, sb0, sb1, sv0, sv1;

    auto fetch = [&](int c) {
        const size_t arow = (size_t)(m0 + lr) * KK + c * BK + lh * 16;
        sa0 = *(const uint4*)(Aph + arow);
        sa1 = *(const uint4*)(Aph + arow + 8);
        sl0 = *(const uint4*)(Apl + arow);
        sl1 = *(const uint4*)(Apl + arow + 8);
        const size_t brow = (size_t)(n0 + lr) * KK + c * BK + lh * 16;
        sb0 = *(const uint4*)(Bph + brow);
        sb1 = *(const uint4*)(Bph + brow + 8);
        sv0 = *(const uint4*)(Bpl + brow);
        sv1 = *(const uint4*)(Bpl + brow + 8);
    };

    auto store_smem = [&](int buf) {
        uint32_t* base = sm + buf * FBUF;
        const uint32_t a0[4] = {sa0.x, sa0.y, sa0.z, sa0.w};
        const uint32_t a1[4] = {sa1.x, sa1.y, sa1.z, sa1.w};
        const uint32_t l0[4] = {sl0.x, sl0.y, sl0.z, sl0.w};
        const uint32_t l1[4] = {sl1.x, sl1.y, sl1.z, sl1.w};
        const uint32_t b0[4] = {sb0.x, sb0.y, sb0.z, sb0.w};
        const uint32_t b1[4] = {sb1.x, sb1.y, sb1.z, sb1.w};
        const uint32_t v0[4] = {sv0.x, sv0.y, sv0.z, sv0.w};
        const uint32_t v1[4] = {sv1.x, sv1.y, sv1.z, sv1.w};
#pragma unroll
        for (int t = 0; t < 4; t++) {
            const int pa = swzA(lh * 1024 + lmt * 128 + (lg * 4 + t) * 4 + lrh * 2);
            *(uint2*)(base + pa)        = make_uint2(a0[t], a1[t]);
            *(uint2*)(base + 2048 + pa) = make_uint2(l0[t], l1[t]);
            const int pb = swzB(lh * 1024 + lnt * 64 + (lg * 4 + t) * 2);
            *(uint2*)(base + 4096 + pb) = make_uint2(b0[t], b1[t]);
            *(uint2*)(base + 6144 + pb) = make_uint2(v0[t], v1[t]);
        }
    };

    float acc[2][8][4];
#pragma unroll
    for (int mi = 0; mi < 2; mi++)
#pragma unroll
        for (int ni = 0; ni < 8; ni++)
#pragma unroll
            for (int q = 0; q < 4; q++) acc[mi][ni][q] = 0.0f;

    // prologue
    fetch(0);
    store_smem(0);
    __syncthreads();

#pragma unroll 1
    for (int c = 0; c < NCK; c++) {
        const int buf = c & 1;
        const bool has_next = (c + 1 < NCK);
        if (has_next) fetch(c + 1);

        const uint32_t* base = sm + buf * FBUF;

#pragma unroll
        for (int kt = 0; kt < 2; kt++) {
            uint4 ah[2], al[2];
#pragma unroll
            for (int mi = 0; mi < 2; mi++) {
                const int p = swzA(kt * 1024 + (warp_m * 2 + mi) * 128 + lane * 4);
                ah[mi] = *(const uint4*)(base + p);
                al[mi] = *(const uint4*)(base + 2048 + p);
            }
#pragma unroll
            for (int ni = 0; ni < 8; ni++) {
                const int p = swzB(kt * 1024 + (warp_n * 8 + ni) * 64 + lane * 2);
                const uint2 bh = *(const uint2*)(base + 4096 + p);
                const uint2 bl = *(const uint2*)(base + 6144 + p);
#pragma unroll
                for (int mi = 0; mi < 2; mi++) {
                    MMA_F16(acc[mi][ni], ah[mi], bh);
                    MMA_F16(acc[mi][ni], ah[mi], bl);
                    MMA_F16(acc[mi][ni], al[mi], bh);
                }
            }
        }

        if (has_next) {
            store_smem(buf ^ 1);
            __syncthreads();
        }
    }

    // ---- epilogue ----
    const int g = lane >> 2, t = lane & 3;
    float* __restrict__ C = (MODE == 0) ? g_U : Cout;
    const float* bptr = (MODE == 0) ? (bias0 + n0)
                      : (gate ? (bias1 + n0 - 512) : (bias0 + n0));

#pragma unroll
    for (int mi = 0; mi < 2; mi++) {
        const int R0 = m0 + warp_m * 32 + mi * 16 + g;
#pragma unroll
        for (int ni = 0; ni < 8; ni++) {
            const int coff = warp_n * 64 + ni * 8 + 2 * t;
            const float2 bb = *(const float2*)(bptr + coff);
            float v0 = acc[mi][ni][0] + bb.x;
            float v1 = acc[mi][ni][1] + bb.y;
            float v2 = acc[mi][ni][2] + bb.x;
            float v3 = acc[mi][ni][3] + bb.y;
            if (gate) {
                v0 = fminf(fmaxf(1.0f / (1.0f + __expf(-v0)), 0.01f), 0.99f);
                v1 = fminf(fmaxf(1.0f / (1.0f + __expf(-v1)), 0.01f), 0.99f);
                v2 = fminf(fmaxf(1.0f / (1.0f + __expf(-v2)), 0.01f), 0.99f);
                v3 = fminf(fmaxf(1.0f / (1.0f + __expf(-v3)), 0.01f), 0.99f);
            }
            const int col = n0 + coff;
            *(float2*)(C + (size_t)R0 * ldc + col)       = make_float2(v0, v1);
            *(float2*)(C + (size_t)(R0 + 8) * ldc + col) = make_float2(v2, v3);
        }
    }
}

// ---------------- chunk-parallel diagonal complex scan ----------------
__global__ void __launch_bounds__(256)
scan_passA(const float* __restrict__ decay_re, const float* __restrict__ decay_im)
{
    const int id = blockIdx.x * blockDim.x + threadIdx.x;
    const int ch = id & (NCH - 1);
    const int c  = id >> 11;
    const int b = ch >> 8;
    const int d = ch & 255;

    const float dr = 1.0f / (1.0f + expf(-decay_re[d]));
    const float di = decay_im[d];

    const float* __restrict__ U = g_U + ((size_t)b * TT + (size_t)c * CHUNK) * KK + d;

    float sr = 0.0f, si = 0.0f;
#pragma unroll 4
    for (int j = 0; j < CHUNK; j++) {
        const float ur = __ldg(U + (size_t)j * KK);
        const float ui = __ldg(U + (size_t)j * KK + 256);
        const float nr = fmaf(sr, dr, fmaf(-si, di, ur));
        const float ni = fmaf(sr, di, fmaf(si, dr, ui));
        sr = nr; si = ni;
    }
    g_E[c * NCH + ch]                = sr;
    g_E[NCHUNK * NCH + c * NCH + ch] = si;
}

__global__ void __launch_bounds__(256)
scan_passB(const float* __restrict__ s0_re, const float* __restrict__ s0_im,
           const float* __restrict__ decay_re, const float* __restrict__ decay_im)
{
    const int id = blockIdx.x * blockDim.x + threadIdx.x;
    const int d = id & 255;

    const float dr = 1.0f / (1.0f + expf(-decay_re[d]));
    const float di = decay_im[d];

    float pr = dr, pi = di;
#pragma unroll
    for (int s = 0; s < 7; s++) {     // d^128
        const float nr = pr * pr - pi * pi;
        const float ni = 2.0f * pr * pi;
        pr = nr; pi = ni;
    }

    float cr = s0_re[id];
    float ci = s0_im[id];
#pragma unroll
    for (int c = 0; c < NCHUNK; c++) {
        g_C[c * NCH + id]                = cr;
        g_C[NCHUNK * NCH + c * NCH + id] = ci;
        const float er = g_E[c * NCH + id];
        const float ei = g_E[NCHUNK * NCH + c * NCH + id];
        const float nr = fmaf(cr, pr, fmaf(-ci, pi, er));
        const float ni = fmaf(cr, pi, fmaf(ci, pr, ei));
        cr = nr; ci = ni;
    }
}

// Pass C: re-scan seeded with carry; write fp16 hi/lo limbs of S directly.
__global__ void __launch_bounds__(256)
scan_passC(const float* __restrict__ decay_re, const float* __restrict__ decay_im)
{
    const int id = blockIdx.x * blockDim.x + threadIdx.x;
    const int ch = id & (NCH - 1);
    const int c  = id >> 11;
    const int b = ch >> 8;
    const int d = ch & 255;

    const float dr = 1.0f / (1.0f + expf(-decay_re[d]));
    const float di = decay_im[d];

    const size_t off = ((size_t)b * TT + (size_t)c * CHUNK) * KK + d;
    const float* __restrict__ U = g_U + off;

    float sr = g_C[c * NCH + ch];
    float si = g_C[NCHUNK * NCH + c * NCH + ch];

#pragma unroll 4
    for (int j = 0; j < CHUNK; j++) {
        const float ur = __ldg(U + (size_t)j * KK);
        const float ui = __ldg(U + (size_t)j * KK + 256);
        const float nr = fmaf(sr, dr, fmaf(-si, di, ur));
        const float ni = fmaf(sr, di, fmaf(si, dr, ui));
        sr = nr; si = ni;
        const size_t a = off + (size_t)j * KK;
        const __half hr = __float2half_rn(nr);
        const __half hi = __float2half_rn(ni);
        g_Sh[a]       = hr;
        g_Sh[a + 256] = hi;
        g_Sl[a]       = __float2half_rn(nr - __half2float(hr));
        g_Sl[a + 256] = __float2half_rn(ni - __half2float(hi));
    }
}

// ---------------- launch ----------------
extern "C" void kernel_launch(void* const* d_in, const int* in_sizes, int n_in,
                              void* d_out, int out_size)
{
    (void)in_sizes; (void)n_in; (void)out_size;
    const float* x_re     = (const float*)d_in[0];
    const float* x_im     = (const float*)d_in[1];
    const float* s0_re    = (const float*)d_in[2];
    const float* s0_im    = (const float*)d_in[3];
    const float* decay_re = (const float*)d_in[4];
    const float* decay_im = (const float*)d_in[5];
    const float* Wm       = (const float*)d_in[6];
    const float* bm       = (const float*)d_in[7];
    const float* Wo       = (const float*)d_in[8];
    const float* bo       = (const float*)d_in[9];
    const float* Wg       = (const float*)d_in[10];
    const float* bg       = (const float*)d_in[11];
    float* out = (float*)d_out;

    static bool configured = false;
    if (!configured) {
        cudaFuncSetAttribute(tc_gemm<0>, cudaFuncAttributeMaxDynamicSharedMemorySize, SM_BYTES);
        cudaFuncSetAttribute(tc_gemm<1>, cudaFuncAttributeMaxDynamicSharedMemorySize, SM_BYTES);
        configured = true;
    }

    // 0) pre-split inputs and weights into fp16 limb planes
    split_x<<<(MM * KK / 4) / 256, 256>>>(x_re, x_im);
    split_w<<<((512 * 512 + 768 * 512) / 4) / 256, 256>>>(Wm, Wo, Wg);

    // 1) u = x_cat @ Wm^T + bm  -> g_U (fp32)
    tc_gemm<0><<<dim3(KK / BN, MM / BM), TPB, SM_BYTES>>>(bm, nullptr, nullptr, KK);

    // 2) chunk-parallel diagonal complex scan g_U -> g_Sh/g_Sl (fp16 limbs)
    scan_passA<<<(NCH * NCHUNK) / 256, 256>>>(decay_re, decay_im);
    scan_passB<<<NCH / 256, 256>>>(s0_re, s0_im, decay_re, decay_im);
    scan_passC<<<(NCH * NCHUNK) / 256, 256>>>(decay_re, decay_im);

    // 3) [source | gate] = s_cat @ [Wo;Wg]^T + [bo;bg]
    tc_gemm<1><<<dim3(768 / BN, MM / BM), TPB, SM_BYTES>>>(bo, bg, out, 768);
}

// round 12
// speedup vs baseline: 1.5615x; 1.0823x over previous
#include <cuda_runtime.h>
#include <cuda_fp16.h>
#include <cstdint>
#include <math.h>

// ---------------- problem constants ----------------
#define BB 8
#define TT 4096
#define DD 256
#define MM (BB*TT)      // 32768
#define KK 512          // 2*D
#define NCH 2048        // B*D

// scan chunking
#define CHUNK 128
#define NCHUNK (TT/CHUNK)   // 32

// mma.sync fp16 GEMM tiling
#define BM 128
#define BN 128
#define BK 32               // K per chunk (2 ktiles of k=16)
#define NCK (KK/BK)         // 16 chunks
#define TPB 256

// smem per stage (b32 words):
//  A: AH/AL fragment words [0,4096)  (hi at +0, lo at +2048)
//  B: interleaved hi/lo uint4 per lane [4096,8192)
#define FBUF 8192
#define NSTAGE 3
#define SM_BYTES (NSTAGE * FBUF * 4)    // 96 KB

// ---------------- scratch (allocation-free) ----------------
__device__ float  g_U[(size_t)MM * KK];    // 64 MB fp32 (scan input)
__device__ __half g_Xh[(size_t)MM * KK];   // hi limb of concat(x_re,x_im)
__device__ __half g_Xl[(size_t)MM * KK];   // lo limb
__device__ __half g_Sh[(size_t)MM * KK];   // hi limb of scanned state
__device__ __half g_Sl[(size_t)MM * KK];   // lo limb
__device__ __half g_W0h[512 * 512], g_W0l[512 * 512];   // Wm limbs
__device__ __half g_W1h[768 * 512], g_W1l[768 * 512];   // [Wo;Wg] limbs
__device__ float g_E[2 * NCHUNK * NCH];
__device__ float g_C[2 * NCHUNK * NCH];

// ---------------- helpers ----------------
__device__ __forceinline__ void split_store4(const float4 v, __half* ph, __half* pl, size_t e) {
    __half2 h0 = __floats2half2_rn(v.x, v.y);
    __half2 h1 = __floats2half2_rn(v.z, v.w);
    float2 f0 = __half22float2(h0), f1 = __half22float2(h1);
    __half2 l0 = __floats2half2_rn(v.x - f0.x, v.y - f0.y);
    __half2 l1 = __floats2half2_rn(v.z - f1.x, v.w - f1.y);
    *(uint2*)(ph + e) = make_uint2(*(uint32_t*)&h0, *(uint32_t*)&h1);
    *(uint2*)(pl + e) = make_uint2(*(uint32_t*)&l0, *(uint32_t*)&l1);
}

// A-region word swizzle (conflict-free for STS.64 writer and LDS.128 reader)
__device__ __forceinline__ int swzA(int idx) { return idx ^ (((idx >> 5) & 3) << 2); }
// B-region lane swizzle: sigma(l) = l ^ (l>>3); conflict-free for both phases
__device__ __forceinline__ int swzL(int l) { return l ^ (l >> 3); }

// a = uint4 (rh0kh0, rh0kh1, rh1kh0, rh1kh1); mma wants rh-major -> x,z,y,w
#define MMA_F16(acc, a, bx, by)                                                 \
    asm volatile("mma.sync.aligned.m16n8k16.row.col.f32.f16.f16.f32 "           \
        "{%0,%1,%2,%3}, {%4,%5,%6,%7}, {%8,%9}, {%0,%1,%2,%3};"                 \
        : "+f"((acc)[0]), "+f"((acc)[1]), "+f"((acc)[2]), "+f"((acc)[3])        \
        : "r"((a).x), "r"((a).z), "r"((a).y), "r"((a).w), "r"(bx), "r"(by))

// ---------------- pre-split kernels ----------------
__global__ void __launch_bounds__(256)
split_x(const float* __restrict__ xre, const float* __restrict__ xim)
{
    const size_t i = (size_t)blockIdx.x * blockDim.x + threadIdx.x;
    const size_t e = i * 4;
    const int m = (int)(e >> 9);
    const int k = (int)(e & 511);
    const float4 v = (k < 256)
        ? *(const float4*)(xre + (size_t)m * 256 + k)
        : *(const float4*)(xim + (size_t)m * 256 + (k - 256));
    split_store4(v, g_Xh, g_Xl, e);
}

__global__ void __launch_bounds__(256)
split_w(const float* __restrict__ Wm, const float* __restrict__ Wo,
        const float* __restrict__ Wg)
{
    const size_t i = (size_t)blockIdx.x * blockDim.x + threadIdx.x;
    const size_t e = i * 4;
    if (e < (size_t)512 * 512) {
        split_store4(*(const float4*)(Wm + e), g_W0h, g_W0l, e);
    } else {
        const size_t e1 = e - (size_t)512 * 512;
        const int n = (int)(e1 >> 9), k = (int)(e1 & 511);
        const float* src = (n < 512) ? (Wo + (size_t)n * 512 + k)
                                     : (Wg + (size_t)(n - 512) * 512 + k);
        split_store4(*(const float4*)src, g_W1h, g_W1l, e1);
    }
}

// ---------------- 3xFP16 mma.sync GEMM ----------------
// C[m,n] = sum_k A[m,k] * W[n,k] + bias[n]
// MODE 0: A = g_X limbs; W = g_W0 limbs; C = g_U fp32 (ldc=512)
// MODE 1: A = g_S limbs; W = g_W1 limbs; gate cols (n>=512): clip(sigmoid); C = out (ldc=768)
template <int MODE>
__global__ void __launch_bounds__(TPB)
tc_gemm(const float* __restrict__ bias0, const float* __restrict__ bias1,
        float* __restrict__ Cout, int ldc)
{
    extern __shared__ uint32_t sm[];

    const int tid = threadIdx.x;
    const int wid = tid >> 5;
    const int lane = tid & 31;
    const int warp_m = wid & 3;      // rows warp_m*32
    const int warp_n = wid >> 2;     // cols warp_n*64
    const int m0 = blockIdx.y * BM;
    const int n0 = blockIdx.x * BN;

    const bool gate = (MODE == 1) && (n0 >= 512);

    const __half* __restrict__ Aph = (MODE == 0) ? g_Xh : g_Sh;
    const __half* __restrict__ Apl = (MODE == 0) ? g_Xl : g_Sl;
    const __half* __restrict__ Bph = (MODE == 0) ? g_W0h : g_W1h;
    const __half* __restrict__ Bpl = (MODE == 0) ? g_W0l : g_W1l;

    // loader mapping: row lr (0..127), ktile lh (0/1)
    const int lr = (tid & 15) + ((tid >> 5) << 4);
    const int lh = (tid >> 4) & 1;
    const int lmt = lr >> 4;          // A m-tile
    const int lrh = (lr >> 3) & 1;    // row-half within 16-row tile
    const int lnt = lr >> 3;          // B n-tile
    const int lg  = lr & 7;

    uint4 sa0, sa1, sl0, sl1, sb0, sb1, sv0, sv1;

    auto fetch = [&](int c) {
        const size_t arow = (size_t)(m0 + lr) * KK + c * BK + lh * 16;
        sa0 = *(const uint4*)(Aph + arow);
        sa1 = *(const uint4*)(Aph + arow + 8);
        sl0 = *(const uint4*)(Apl + arow);
        sl1 = *(const uint4*)(Apl + arow + 8);
        const size_t brow = (size_t)(n0 + lr) * KK + c * BK + lh * 16;
        sb0 = *(const uint4*)(Bph + brow);
        sb1 = *(const uint4*)(Bph + brow + 8);
        sv0 = *(const uint4*)(Bpl + brow);
        sv1 = *(const uint4*)(Bpl + brow + 8);
    };

    auto store_smem = [&](int buf) {
        uint32_t* base = sm + buf * FBUF;
        const uint32_t a0[4] = {sa0.x, sa0.y, sa0.z, sa0.w};
        const uint32_t a1[4] = {sa1.x, sa1.y, sa1.z, sa1.w};
        const uint32_t l0[4] = {sl0.x, sl0.y, sl0.z, sl0.w};
        const uint32_t l1[4] = {sl1.x, sl1.y, sl1.z, sl1.w};
        const uint32_t b0[4] = {sb0.x, sb0.y, sb0.z, sb0.w};
        const uint32_t b1[4] = {sb1.x, sb1.y, sb1.z, sb1.w};
        const uint32_t v0[4] = {sv0.x, sv0.y, sv0.z, sv0.w};
        const uint32_t v1[4] = {sv1.x, sv1.y, sv1.z, sv1.w};
#pragma unroll
        for (int t = 0; t < 4; t++) {
            const int lw = lg * 4 + t;
            // A region: hi at swzA(idx), lo at +2048
            const int pa = swzA(lh * 1024 + lmt * 128 + lw * 4 + lrh * 2);
            *(uint2*)(base + pa)        = make_uint2(a0[t], a1[t]);
            *(uint2*)(base + 2048 + pa) = make_uint2(l0[t], l1[t]);
            // B region: interleaved {bh_kh0, bh_kh1, bl_kh0, bl_kh1} per lane
            const int pb = 4096 + lh * 2048 + lnt * 128 + swzL(lw) * 4;
            *(uint4*)(base + pb) = make_uint4(b0[t], b1[t], v0[t], v1[t]);
        }
    };

    float acc[2][8][4];
#pragma unroll
    for (int mi = 0; mi < 2; mi++)
#pragma unroll
        for (int ni = 0; ni < 8; ni++)
#pragma unroll
            for (int q = 0; q < 4; q++) acc[mi][ni][q] = 0.0f;

    // prologue: fill stage 0, prefetch chunk 1 into regs
    fetch(0);
    store_smem(0);
    fetch(1);
    __syncthreads();

    const int lsw = swzL(lane) * 4;

#pragma unroll 1
    for (int c = 0; c < NCK; c++) {
        // store chunk c+1 (staged regs), then prefetch chunk c+2
        if (c + 1 < NCK) store_smem((c + 1) % NSTAGE);
        if (c + 2 < NCK) fetch(c + 2);
        __syncthreads();

        const uint32_t* base = sm + (c % NSTAGE) * FBUF;

#pragma unroll
        for (int kt = 0; kt < 2; kt++) {
            uint4 ah[2], al[2], bq[8];
#pragma unroll
            for (int mi = 0; mi < 2; mi++) {
                const int p = swzA(kt * 1024 + (warp_m * 2 + mi) * 128 + lane * 4);
                ah[mi] = *(const uint4*)(base + p);
                al[mi] = *(const uint4*)(base + 2048 + p);
            }
#pragma unroll
            for (int ni = 0; ni < 8; ni++) {
                const int p = 4096 + kt * 2048 + (warp_n * 8 + ni) * 128 + lsw;
                bq[ni] = *(const uint4*)(base + p);
            }
            // pass 0: Ah*Bh — 16 independent accumulators
#pragma unroll
            for (int ni = 0; ni < 8; ni++)
#pragma unroll
                for (int mi = 0; mi < 2; mi++)
                    MMA_F16(acc[mi][ni], ah[mi], bq[ni].x, bq[ni].y);
            // pass 1: Ah*Bl
#pragma unroll
            for (int ni = 0; ni < 8; ni++)
#pragma unroll
                for (int mi = 0; mi < 2; mi++)
                    MMA_F16(acc[mi][ni], ah[mi], bq[ni].z, bq[ni].w);
            // pass 2: Al*Bh
#pragma unroll
            for (int ni = 0; ni < 8; ni++)
#pragma unroll
                for (int mi = 0; mi < 2; mi++)
                    MMA_F16(acc[mi][ni], al[mi], bq[ni].x, bq[ni].y);
        }
    }

    // ---- epilogue ----
    const int g = lane >> 2, t = lane & 3;
    float* __restrict__ C = (MODE == 0) ? g_U : Cout;
    const float* bptr = (MODE == 0) ? (bias0 + n0)
                      : (gate ? (bias1 + n0 - 512) : (bias0 + n0));

#pragma unroll
    for (int mi = 0; mi < 2; mi++) {
        const int R0 = m0 + warp_m * 32 + mi * 16 + g;
#pragma unroll
        for (int ni = 0; ni < 8; ni++) {
            const int coff = warp_n * 64 + ni * 8 + 2 * t;
            const float2 bb = *(const float2*)(bptr + coff);
            float v0 = acc[mi][ni][0] + bb.x;
            float v1 = acc[mi][ni][1] + bb.y;
            float v2 = acc[mi][ni][2] + bb.x;
            float v3 = acc[mi][ni][3] + bb.y;
            if (gate) {
                v0 = fminf(fmaxf(1.0f / (1.0f + __expf(-v0)), 0.01f), 0.99f);
                v1 = fminf(fmaxf(1.0f / (1.0f + __expf(-v1)), 0.01f), 0.99f);
                v2 = fminf(fmaxf(1.0f / (1.0f + __expf(-v2)), 0.01f), 0.99f);
                v3 = fminf(fmaxf(1.0f / (1.0f + __expf(-v3)), 0.01f), 0.99f);
            }
            const int col = n0 + coff;
            *(float2*)(C + (size_t)R0 * ldc + col)       = make_float2(v0, v1);
            *(float2*)(C + (size_t)(R0 + 8) * ldc + col) = make_float2(v2, v3);
        }
    }
}

// ---------------- chunk-parallel diagonal complex scan ----------------
__global__ void __launch_bounds__(256)
scan_passA(const float* __restrict__ decay_re, const float* __restrict__ decay_im)
{
    const int id = blockIdx.x * blockDim.x + threadIdx.x;
    const int ch = id & (NCH - 1);
    const int c  = id >> 11;
    const int b = ch >> 8;
    const int d = ch & 255;

    const float dr = 1.0f / (1.0f + expf(-decay_re[d]));
    const float di = decay_im[d];

    const float* __restrict__ U = g_U + ((size_t)b * TT + (size_t)c * CHUNK) * KK + d;

    float sr = 0.0f, si = 0.0f;
#pragma unroll 4
    for (int j = 0; j < CHUNK; j++) {
        const float ur = __ldg(U + (size_t)j * KK);
        const float ui = __ldg(U + (size_t)j * KK + 256);
        const float nr = fmaf(sr, dr, fmaf(-si, di, ur));
        const float ni = fmaf(sr, di, fmaf(si, dr, ui));
        sr = nr; si = ni;
    }
    g_E[c * NCH + ch]                = sr;
    g_E[NCHUNK * NCH + c * NCH + ch] = si;
}

__global__ void __launch_bounds__(256)
scan_passB(const float* __restrict__ s0_re, const float* __restrict__ s0_im,
           const float* __restrict__ decay_re, const float* __restrict__ decay_im)
{
    const int id = blockIdx.x * blockDim.x + threadIdx.x;
    const int d = id & 255;

    const float dr = 1.0f / (1.0f + expf(-decay_re[d]));
    const float di = decay_im[d];

    float pr = dr, pi = di;
#pragma unroll
    for (int s = 0; s < 7; s++) {     // d^128
        const float nr = pr * pr - pi * pi;
        const float ni = 2.0f * pr * pi;
        pr = nr; pi = ni;
    }

    float cr = s0_re[id];
    float ci = s0_im[id];
#pragma unroll
    for (int c = 0; c < NCHUNK; c++) {
        g_C[c * NCH + id]                = cr;
        g_C[NCHUNK * NCH + c * NCH + id] = ci;
        const float er = g_E[c * NCH + id];
        const float ei = g_E[NCHUNK * NCH + c * NCH + id];
        const float nr = fmaf(cr, pr, fmaf(-ci, pi, er));
        const float ni = fmaf(cr, pi, fmaf(ci, pr, ei));
        cr = nr; ci = ni;
    }
}

// Pass C: re-scan seeded with carry; write fp16 hi/lo limbs of S directly.
__global__ void __launch_bounds__(256)
scan_passC(const float* __restrict__ decay_re, const float* __restrict__ decay_im)
{
    const int id = blockIdx.x * blockDim.x + threadIdx.x;
    const int ch = id & (NCH - 1);
    const int c  = id >> 11;
    const int b = ch >> 8;
    const int d = ch & 255;

    const float dr = 1.0f / (1.0f + expf(-decay_re[d]));
    const float di = decay_im[d];

    const size_t off = ((size_t)b * TT + (size_t)c * CHUNK) * KK + d;
    const float* __restrict__ U = g_U + off;

    float sr = g_C[c * NCH + ch];
    float si = g_C[NCHUNK * NCH + c * NCH + ch];

#pragma unroll 4
    for (int j = 0; j < CHUNK; j++) {
        const float ur = __ldg(U + (size_t)j * KK);
        const float ui = __ldg(U + (size_t)j * KK + 256);
        const float nr = fmaf(sr, dr, fmaf(-si, di, ur));
        const float ni = fmaf(sr, di, fmaf(si, dr, ui));
        sr = nr; si = ni;
        const size_t a = off + (size_t)j * KK;
        const __half hr = __float2half_rn(nr);
        const __half hi = __float2half_rn(ni);
        g_Sh[a]       = hr;
        g_Sh[a + 256] = hi;
        g_Sl[a]       = __float2half_rn(nr - __half2float(hr));
        g_Sl[a + 256] = __float2half_rn(ni - __half2float(hi));
    }
}

// ---------------- launch ----------------
extern "C" void kernel_launch(void* const* d_in, const int* in_sizes, int n_in,
                              void* d_out, int out_size)
{
    (void)in_sizes; (void)n_in; (void)out_size;
    const float* x_re     = (const float*)d_in[0];
    const float* x_im     = (const float*)d_in[1];
    const float* s0_re    = (const float*)d_in[2];
    const float* s0_im    = (const float*)d_in[3];
    const float* decay_re = (const float*)d_in[4];
    const float* decay_im = (const float*)d_in[5];
    const float* Wm       = (const float*)d_in[6];
    const float* bm       = (const float*)d_in[7];
    const float* Wo       = (const float*)d_in[8];
    const float* bo       = (const float*)d_in[9];
    const float* Wg       = (const float*)d_in[10];
    const float* bg       = (const float*)d_in[11];
    float* out = (float*)d_out;

    static bool configured = false;
    if (!configured) {
        cudaFuncSetAttribute(tc_gemm<0>, cudaFuncAttributeMaxDynamicSharedMemorySize, SM_BYTES);
        cudaFuncSetAttribute(tc_gemm<1>, cudaFuncAttributeMaxDynamicSharedMemorySize, SM_BYTES);
        configured = true;
    }

    // 0) pre-split inputs and weights into fp16 limb planes
    split_x<<<(MM * KK / 4) / 256, 256>>>(x_re, x_im);
    split_w<<<((512 * 512 + 768 * 512) / 4) / 256, 256>>>(Wm, Wo, Wg);

    // 1) u = x_cat @ Wm^T + bm  -> g_U (fp32)
    tc_gemm<0><<<dim3(KK / BN, MM / BM), TPB, SM_BYTES>>>(bm, nullptr, nullptr, KK);

    // 2) chunk-parallel diagonal complex scan g_U -> g_Sh/g_Sl (fp16 limbs)
    scan_passA<<<(NCH * NCHUNK) / 256, 256>>>(decay_re, decay_im);
    scan_passB<<<NCH / 256, 256>>>(s0_re, s0_im, decay_re, decay_im);
    scan_passC<<<(NCH * NCHUNK) / 256, 256>>>(decay_re, decay_im);

    // 3) [source | gate] = s_cat @ [Wo;Wg]^T + [bo;bg]
    tc_gemm<1><<<dim3(768 / BN, MM / BM), TPB, SM_BYTES>>>(bo, bg, out, 768);
}